// round 17
// baseline (speedup 1.0000x reference)
#include <cuda_runtime.h>
#include <cuda_bf16.h>
#include <cstdint>

#define B_   64
#define TQ_  2048
#define TK_  2048
#define D_   64
#define STRW 68     // words per smem row (64 + 4 pad: conflict-free quad access)
#define MROWS 128   // q-rows per CTA (kernel 1)
#define NT_  (TK_ / 64)

// Per-row 1/rowsum, kernel1 -> kernel2. Static device scratch.
__device__ float g_rowinv[B_ * TQ_];
// Mask element kind: 1 = 1-byte elements (bool/uint8), 0 = 4-byte (int32/float32)
__device__ int g_mask_kind;

__global__ void detect_mask_kind(const unsigned char* __restrict__ m) {
    __shared__ int flag;
    int tid = threadIdx.x;
    if (tid == 0) flag = 0;
    __syncthreads();
    const uint4* m4 = (const uint4*)m;
    uint4 u = m4[tid];
    unsigned w[4] = {u.x, u.y, u.z, u.w};
    int bad = 0;
#pragma unroll
    for (int i = 0; i < 4; i++) {
        unsigned x = w[i];
        if (!(x == 0u || x == 1u || x == 0x3F800000u)) bad = 1;
    }
    if (bad) atomicOr(&flag, 1);
    __syncthreads();
    if (tid == 0) g_mask_kind = flag ? 1 : 0;
}

// exp(s/8) via MUFU.EX2: 1 FMUL + 1 MUFU.
__device__ __forceinline__ float fexp8(float s) {
    float r;
    float x = s * 0.18033688011112042f;   // log2(e)/8
    asm("ex2.approx.f32 %0, %1;" : "=f"(r) : "f"(x));
    return r;
}

__device__ __forceinline__ unsigned cvt_tf32(float x) {
    unsigned r;
    asm("cvt.rna.tf32.f32 %0, %1;" : "=r"(r) : "f"(x));
    return r;
}

__device__ __forceinline__ void mma8(float c[4], const unsigned a[4],
                                     unsigned b0, unsigned b1) {
    asm("mma.sync.aligned.m16n8k8.row.col.f32.tf32.tf32.f32 "
        "{%0,%1,%2,%3}, {%4,%5,%6,%7}, {%8,%9}, {%0,%1,%2,%3};"
        : "+f"(c[0]), "+f"(c[1]), "+f"(c[2]), "+f"(c[3])
        : "r"(a[0]), "r"(a[1]), "r"(a[2]), "r"(a[3]), "r"(b0), "r"(b1));
}

__device__ __forceinline__ void cp16(void* sdst, const void* gsrc) {
    unsigned s = (unsigned)__cvta_generic_to_shared(sdst);
    asm volatile("cp.async.cg.shared.global [%0], [%1], 16;\n" :: "r"(s), "l"(gsrc));
}
__device__ __forceinline__ void cp_commit() {
    asm volatile("cp.async.commit_group;\n");
}
template <int N>
__device__ __forceinline__ void cp_wait() {
    asm volatile("cp.async.wait_group %0;\n" :: "n"(N));
}

// convert a 16B smem chunk of 4 f32 to tf32 bits, in place
__device__ __forceinline__ void cvt_chunk(float* p) {
    float4 x = *(float4*)p;
    uint4 u = make_uint4(cvt_tf32(x.x), cvt_tf32(x.y), cvt_tf32(x.z), cvt_tf32(x.w));
    *(uint4*)p = u;
}

// ---------------------------------------------------------------------------
// KERNEL 1: QK + exp. CTA: 128 q-rows x full TK, 512 threads / 16 warps.
// Per tile: deferred coalesced store of e(kt-1), prefetch K/mask(kt+1),
// QK(kt) mma, MUFU exp -> Ps[cur] (tf32 bits), rowsum. One sync per tile.
// No V, no PV, no O — those moved to pv_rescale. Writes UNNORMALIZED tf32
// e to attn and 1/rowsum to g_rowinv.
// ---------------------------------------------------------------------------
__global__ __launch_bounds__(512, 1)
void attn_qk(const float* __restrict__ q, const float* __restrict__ k,
             const unsigned char* __restrict__ mask, float* __restrict__ attn) {
    extern __shared__ __align__(16) unsigned char smemraw[];
    float* Kb = (float*)smemraw;                         // [2][64][STRW] tf32 K
    float* Psb = Kb + 2 * 64 * STRW;                     // [2][128][STRW] tf32 e
    unsigned char* Msb = (unsigned char*)(Psb + 2 * MROWS * STRW);  // [2][128*80]
    float* RowRed = (float*)(Msb + 2 * MROWS * 80);      // [128]

#define KS(st, r, c) Kb[(st) * (64 * STRW) + (r) * STRW + (c)]
#define KSU(st, r, c) (*(unsigned*)&KS(st, r, c))
#define PS(st, r, c) Psb[(st) * (MROWS * STRW) + (r) * STRW + (c)]
#define MS(st, i)    Msb[(st) * (MROWS * 80) + (i)]

    const int tid = threadIdx.x;
    const int wid = tid >> 5;
    const int lane = tid & 31;
    const int bb = blockIdx.y;
    const int qbase = blockIdx.x * MROWS;

    const float* qp = q + ((size_t)bb * TQ_ + qbase) * D_;
    const float* kp = k + (size_t)bb * TK_ * D_;
    float* arow = attn + ((size_t)bb * TQ_ + qbase) * TK_;
    const size_t mbase = ((size_t)bb * TQ_ + qbase) * TK_;
    const int mask_is_byte = g_mask_kind;

    if (tid < MROWS) RowRed[tid] = 0.0f;

    const int rr = tid >> 4;          // 0..31 ; K rows rr, rr+32
    const int c4 = (tid & 15) * 4;
    const int mr = tid >> 2;          // 0..127
    const int mseg = (tid & 3) * 16;

    // ---- prologue: prefetch K(0), mask(0) ----
#pragma unroll
    for (int j = 0; j < 2; j++)
        cp16(&KS(0, rr + j * 32, c4), kp + (size_t)(rr + j * 32) * D_ + c4);
    if (mask_is_byte) {
        cp16(&MS(0, mr * 80 + mseg), mask + mbase + (size_t)mr * TK_ + mseg);
    } else {
        const int* mi = (const int*)mask;
#pragma unroll
        for (int j = 0; j < 4; j++) {
            int i4 = tid + j * 512;
            int r = i4 >> 4, cc = (i4 & 15) * 4;
            int4 mm = *(const int4*)(mi + mbase + (size_t)r * TK_ + cc);
            uchar4 pk;
            pk.x = mm.x ? 1 : 0; pk.y = mm.y ? 1 : 0;
            pk.z = mm.z ? 1 : 0; pk.w = mm.w ? 1 : 0;
            *(uchar4*)&MS(0, r * 80 + cc) = pk;
        }
    }
    cp_commit();

    // Stage Q (128x64) into Ps[0] (raw f32), then to tf32 A fragments
#pragma unroll
    for (int j = 0; j < 4; j++) {
        int r = rr + j * 32;
        *(float4*)&PS(0, r, c4) = *(const float4*)(qp + r * D_ + c4);
    }
    __syncthreads();

    const int kg = wid & 1;
    const int r0 = (wid >> 1) * 16 + (lane >> 2);    // 0..127
    const int qc = lane & 3;

    unsigned qa[8][4];
#pragma unroll
    for (int kc = 0; kc < 8; kc++) {
        qa[kc][0] = cvt_tf32(PS(0, r0, kc * 8 + qc));
        qa[kc][1] = cvt_tf32(PS(0, r0 + 8, kc * 8 + qc));
        qa[kc][2] = cvt_tf32(PS(0, r0, kc * 8 + qc + 4));
        qa[kc][3] = cvt_tf32(PS(0, r0 + 8, kc * 8 + qc + 4));
    }
    cp_wait<0>();     // K0/M0 arrived
#pragma unroll
    for (int j = 0; j < 2; j++) cvt_chunk(&KS(0, rr + j * 32, c4));
    __syncthreads();  // qa built; Ps[0] free; converted K tile visible to all

    float rs0 = 0.0f, rs1 = 0.0f;

    for (int kt = 0; kt < NT_; kt++) {
        const int kb = kt * 64;
        const int cur = kt & 1;
        const int prv = cur ^ 1;

        // --- deferred coalesced store of e(kt-1) ---
        if (kt > 0) {
#pragma unroll
            for (int j = 0; j < 4; j++) {
                int i = tid + j * 512;
                int r = i >> 4, cc = (i & 15) * 4;
                *(float4*)(arow + (size_t)r * TK_ + (kb - 64) + cc) =
                    *(float4*)&PS(prv, r, cc);
            }
        }

        // --- prefetch: K(kt+1)+mask(kt+1) -> [prv] ---
        if (kt + 1 < NT_) {
            const int kb2 = kb + 64;
#pragma unroll
            for (int j = 0; j < 2; j++) {
                int r = rr + j * 32;
                cp16(&KS(prv, r, c4), kp + (size_t)(kb2 + r) * D_ + c4);
            }
            if (mask_is_byte) {
                cp16(&MS(prv, mr * 80 + mseg),
                     mask + mbase + (size_t)mr * TK_ + kb2 + mseg);
            } else {
                const int* mi = (const int*)mask;
#pragma unroll
                for (int j = 0; j < 4; j++) {
                    int i4 = tid + j * 512;
                    int r = i4 >> 4, cc = (i4 & 15) * 4;
                    int4 mm = *(const int4*)(mi + mbase + (size_t)r * TK_ + kb2 + cc);
                    uchar4 pk;
                    pk.x = mm.x ? 1 : 0; pk.y = mm.y ? 1 : 0;
                    pk.z = mm.z ? 1 : 0; pk.w = mm.w ? 1 : 0;
                    *(uchar4*)&MS(prv, r * 80 + cc) = pk;
                }
            }
        }
        cp_commit();

        // --- S = Q * K^T, warp's 16x32 subtile ---
        float c[4][4];
#pragma unroll
        for (int nt = 0; nt < 4; nt++)
#pragma unroll
            for (int i = 0; i < 4; i++) c[nt][i] = 0.0f;

#pragma unroll
        for (int kc = 0; kc < 8; kc++) {
#pragma unroll
            for (int nt = 0; nt < 4; nt++) {
                int key = kg * 32 + nt * 8 + (lane >> 2);
                mma8(c[nt], qa[kc], KSU(cur, key, kc * 8 + qc),
                     KSU(cur, key, kc * 8 + qc + 4));
            }
        }

        // --- mask + MUFU exp -> Ps[cur] as tf32 bits, rowsum ---
#pragma unroll
        for (int nt = 0; nt < 4; nt++) {
            int col = kg * 32 + nt * 8 + 2 * qc;
            float e00 = MS(cur, r0 * 80 + col)           ? 0.0f : fexp8(c[nt][0]);
            float e01 = MS(cur, r0 * 80 + col + 1)       ? 0.0f : fexp8(c[nt][1]);
            float e10 = MS(cur, (r0 + 8) * 80 + col)     ? 0.0f : fexp8(c[nt][2]);
            float e11 = MS(cur, (r0 + 8) * 80 + col + 1) ? 0.0f : fexp8(c[nt][3]);
            rs0 += e00 + e01;
            rs1 += e10 + e11;
            *(uint2*)&PS(cur, r0, col) = make_uint2(cvt_tf32(e00), cvt_tf32(e01));
            *(uint2*)&PS(cur, r0 + 8, col) = make_uint2(cvt_tf32(e10), cvt_tf32(e11));
        }

        cp_wait<0>();     // K(kt+1)/mask(kt+1) landed
        if (kt + 1 < NT_) {
#pragma unroll
            for (int j = 0; j < 2; j++) cvt_chunk(&KS(prv, rr + j * 32, c4));
        }
        __syncthreads();  // publishes Ps[cur] + converted K tile
    }

    // ---- flush: store last e tile ----
    {
        const int lst = (NT_ - 1) & 1;
        const int kb = (NT_ - 1) * 64;
#pragma unroll
        for (int j = 0; j < 4; j++) {
            int i = tid + j * 512;
            int r = i >> 4, cc = (i & 15) * 4;
            *(float4*)(arow + (size_t)r * TK_ + kb + cc) = *(float4*)&PS(lst, r, cc);
        }
    }

    // ---- rowsum reduction -> g_rowinv ----
    rs0 += __shfl_xor_sync(0xFFFFFFFFu, rs0, 1);
    rs0 += __shfl_xor_sync(0xFFFFFFFFu, rs0, 2);
    rs1 += __shfl_xor_sync(0xFFFFFFFFu, rs1, 1);
    rs1 += __shfl_xor_sync(0xFFFFFFFFu, rs1, 2);
    if (qc == 0) {
        atomicAdd(&RowRed[r0], rs0);
        atomicAdd(&RowRed[r0 + 8], rs1);
    }
    __syncthreads();
    if (tid < MROWS)
        g_rowinv[bb * TQ_ + qbase + tid] = 1.0f / RowRed[tid];
}

// ---------------------------------------------------------------------------
// KERNEL 2: PV + rescale, fused. CTA: 64 q-rows x full TK, 256 threads,
// 2 CTAs/SM. Streams the unnormalized e tiles (which it must read anyway to
// normalize), writes e*inv back, and accumulates O = e·V on the tensor pipe
// underneath the DRAM stream. e is already tf32 bits -> raw A operands.
// ---------------------------------------------------------------------------
__global__ __launch_bounds__(256, 2)
void pv_rescale(const float* __restrict__ v, float* __restrict__ out,
                float* __restrict__ attn) {
    extern __shared__ __align__(16) unsigned char smemraw[];
    float* Eb = (float*)smemraw;                 // [2][64][STRW] tf32 e
    float* Vb = Eb + 2 * 64 * STRW;              // [2][64][STRW] tf32 V
    float* Inv = Vb + 2 * 64 * STRW;             // [64]

#define ES(st, r, c) Eb[(st) * (64 * STRW) + (r) * STRW + (c)]
#define ESU(st, r, c) (*(unsigned*)&ES(st, r, c))
#define VS2(st, r, c) Vb[(st) * (64 * STRW) + (r) * STRW + (c)]
#define VSU2(st, r, c) (*(unsigned*)&VS2(st, r, c))

    const int tid = threadIdx.x;
    const int wid = tid >> 5;
    const int lane = tid & 31;
    const int bb = blockIdx.y;
    const int qbase = blockIdx.x * 64;

    const float* vp = v + (size_t)bb * TK_ * D_;
    float* arow = attn + ((size_t)bb * TQ_ + qbase) * TK_;

    if (tid < 64) Inv[tid] = g_rowinv[bb * TQ_ + qbase + tid];

    // staging coords: 64x64 tile, 256 threads -> 4 chunks of 16B each
    const int rr = tid >> 4;          // 0..15 ; rows rr + j*16
    const int c4 = (tid & 15) * 4;

    // ---- prologue: prefetch E(0), V(0) ----
#pragma unroll
    for (int j = 0; j < 4; j++) {
        int r = rr + j * 16;
        cp16(&ES(0, r, c4), arow + (size_t)r * TK_ + c4);
        cp16(&VS2(0, r, c4), vp + (size_t)r * D_ + c4);
    }
    cp_commit();
    cp_wait<0>();
#pragma unroll
    for (int j = 0; j < 4; j++) cvt_chunk(&VS2(0, rr + j * 16, c4));
    __syncthreads();

    const int kg = wid & 1;
    const int r0 = (wid >> 1) * 16 + (lane >> 2);    // 0..63
    const int qc = lane & 3;
    const int g = lane >> 2;

    float oacc[4][4];
#pragma unroll
    for (int nt = 0; nt < 4; nt++)
#pragma unroll
        for (int i = 0; i < 4; i++) oacc[nt][i] = 0.0f;

    for (int kt = 0; kt < NT_; kt++) {
        const int kb = kt * 64;
        const int cur = kt & 1;
        const int prv = cur ^ 1;

        // --- prefetch E(kt+1), V(kt+1) -> [prv] ---
        if (kt + 1 < NT_) {
            const int kb2 = kb + 64;
#pragma unroll
            for (int j = 0; j < 4; j++) {
                int r = rr + j * 16;
                cp16(&ES(prv, r, c4), arow + (size_t)r * TK_ + kb2 + c4);
                cp16(&VS2(prv, r, c4), vp + (size_t)(kb2 + r) * D_ + c4);
            }
        }
        cp_commit();

        // --- O += e * V : raw tf32-bit A operands, staged tf32 V ---
#pragma unroll
        for (int kc = 0; kc < 8; kc++) {
            unsigned a[4];
            a[0] = ESU(cur, r0, kc * 8 + qc);
            a[1] = ESU(cur, r0 + 8, kc * 8 + qc);
            a[2] = ESU(cur, r0, kc * 8 + qc + 4);
            a[3] = ESU(cur, r0 + 8, kc * 8 + qc + 4);
#pragma unroll
            for (int nt = 0; nt < 4; nt++) {
                int dcol = kg * 32 + nt * 8 + g;
                mma8(oacc[nt], a, VSU2(cur, kc * 8 + qc, dcol),
                     VSU2(cur, kc * 8 + qc + 4, dcol));
            }
        }

        // --- normalize + write back this e tile ---
#pragma unroll
        for (int j = 0; j < 4; j++) {
            int r = rr + j * 16;
            float inv = Inv[r];
            float4 x = *(float4*)&ES(cur, r, c4);
            x.x *= inv; x.y *= inv; x.z *= inv; x.w *= inv;
            *(float4*)(arow + (size_t)r * TK_ + kb + c4) = x;
        }

        cp_wait<0>();     // E(kt+1), V(kt+1) landed
        if (kt + 1 < NT_) {
#pragma unroll
            for (int j = 0; j < 4; j++) cvt_chunk(&VS2(prv, rr + j * 16, c4));
        }
        __syncthreads();  // guards buffer reuse
    }

    // ---- write O scaled by inv ----
    {
        float inv0 = Inv[r0];
        float inv1 = Inv[r0 + 8];
#pragma unroll
        for (int nt = 0; nt < 4; nt++) {
            int dcol = kg * 32 + nt * 8 + 2 * qc;
            size_t oi = ((size_t)(bb * TQ_ + qbase + r0)) * D_ + dcol;
            *(float2*)(out + oi) =
                make_float2(oacc[nt][0] * inv0, oacc[nt][1] * inv0);
            *(float2*)(out + oi + (size_t)8 * D_) =
                make_float2(oacc[nt][2] * inv1, oacc[nt][3] * inv1);
        }
    }
}

static const int kSmem1 =
    (2 * 64 * STRW + 2 * MROWS * STRW) * 4 + 2 * MROWS * 80 + MROWS * 4;
static const int kSmem2 = (4 * 64 * STRW) * 4 + 64 * 4;

extern "C" void kernel_launch(void* const* d_in, const int* in_sizes, int n_in,
                              void* d_out, int out_size) {
    const float* q = (const float*)d_in[0];
    const float* k = (const float*)d_in[1];
    const float* v = (const float*)d_in[2];
    const unsigned char* mask = (const unsigned char*)d_in[3];

    float* out = (float*)d_out;                 // [B, TQ, D]
    float* attn = out + (size_t)B_ * TQ_ * D_;  // [B, TQ, TK]

    cudaFuncSetAttribute(attn_qk, cudaFuncAttributeMaxDynamicSharedMemorySize,
                         kSmem1);
    cudaFuncSetAttribute(pv_rescale, cudaFuncAttributeMaxDynamicSharedMemorySize,
                         kSmem2);

    detect_mask_kind<<<1, 256>>>(mask);

    dim3 grid1(TQ_ / MROWS, B_);
    attn_qk<<<grid1, 512, kSmem1>>>(q, k, mask, attn);

    dim3 grid2(TQ_ / 64, B_);
    pv_rescale<<<grid2, 256, kSmem2>>>(v, out, attn);
}